// round 5
// baseline (speedup 1.0000x reference)
#include <cuda_runtime.h>
#include <cuda_bf16.h>
#include <cstdint>

// MoE dense 8-expert: D_IN=6, H=32, D_OUT=2, B=1M, fp32.
// R5: identical compute structure to R4 (mma.sync bf16 3-split layer-2,
// fragment-layout scalar layer-1, per-lane precomputed B fragments) but with
// forced 4 CTAs/SM residency (launch_bounds(128,4), grid=4*SMs) to fix the
// measured occupancy/issue bottleneck (occ 12.2%, issue 48.5%).

#define ED 8
#define DI 6
#define HH 32
#define DO 2

typedef unsigned long long u64;
typedef unsigned int u32;

// ---- helpers ----
__device__ __forceinline__ void ffma2_acc(u64& acc, u64 a, u64 b) {
    asm("fma.rn.f32x2 %0, %1, %2, %0;" : "+l"(acc) : "l"(a), "l"(b));
}
__device__ __forceinline__ u64 pack_dup(float v) {
    u64 r; asm("mov.b64 %0, {%1, %1};" : "=l"(r) : "r"(__float_as_uint(v))); return r;
}
__device__ __forceinline__ float2 unpack2(u64 v) {
    float2 f; asm("mov.b64 {%0, %1}, %2;" : "=f"(f.x), "=f"(f.y) : "l"(v)); return f;
}
// pack two f32 -> bf16x2 (element0 = lo arg, element1 = hi arg)
__device__ __forceinline__ u32 bf16x2_of(float lo_e, float hi_e) {
    u32 r; asm("cvt.rn.bf16x2.f32 %0, %1, %2;" : "=r"(r) : "f"(hi_e), "f"(lo_e)); return r;
}
__device__ __forceinline__ float bflo(u32 p) { return __uint_as_float(p << 16); }
__device__ __forceinline__ float bfhi(u32 p) { return __uint_as_float(p & 0xffff0000u); }

__device__ __forceinline__ void mma_bf16(float& d0, float& d1, float& d2, float& d3,
                                         u32 a0, u32 a1, u32 a2, u32 a3,
                                         u32 b0, u32 b1) {
    asm("mma.sync.aligned.m16n8k16.row.col.f32.bf16.bf16.f32 "
        "{%0,%1,%2,%3}, {%4,%5,%6,%7}, {%8,%9}, {%0,%1,%2,%3};"
        : "+f"(d0), "+f"(d1), "+f"(d2), "+f"(d3)
        : "r"(a0), "r"(a1), "r"(a2), "r"(a3), "r"(b0), "r"(b1));
}

__global__ __launch_bounds__(128, 4)
void moe_mma_kernel(const float* __restrict__ gx,
                    const float* __restrict__ gW1, const float* __restrict__ gb1,
                    const float* __restrict__ gW2, const float* __restrict__ gb2,
                    const float* __restrict__ gW3, const float* __restrict__ gb3,
                    const float* __restrict__ gWg1, const float* __restrict__ gbg1,
                    const float* __restrict__ gWg2, const float* __restrict__ gbg2,
                    float* __restrict__ gout, int B, int NT)
{
    __shared__ __align__(16) float sx[4 * 192];              // per-warp x tiles
    __shared__ __align__(16) char  sBfrag[ED * 8 * 32 * 16]; // [e][chunk0-3 hi,4-7 lo][lane][16B]
    __shared__ __align__(16) float sW1[ED * DI * HH];
    __shared__ __align__(16) float sb1[ED * HH];
    __shared__ __align__(16) float sb2[ED * HH];
    __shared__ __align__(16) float sW3[ED * HH * DO];
    __shared__ __align__(16) float sb3[ED * DO];
    __shared__ __align__(16) float sWg1[DI * HH];
    __shared__ __align__(16) float sbg1[HH];
    __shared__ __align__(16) float sWg2[HH * ED];
    __shared__ __align__(16) float sbg2[ED];

    const int tid  = threadIdx.x;
    const int w    = tid >> 5;
    const int lane = tid & 31;
    const int g    = lane >> 2;   // groupID
    const int q    = lane & 3;    // threadID in group

    // ---- stage small weights ----
    for (int i = tid; i < ED * DI * HH; i += 128) sW1[i]  = gW1[i];
    for (int i = tid; i < ED * HH;      i += 128) sb1[i]  = gb1[i];
    for (int i = tid; i < ED * HH;      i += 128) sb2[i]  = gb2[i];
    for (int i = tid; i < ED * HH * DO; i += 128) sW3[i]  = gW3[i];
    for (int i = tid; i < ED * DO;      i += 128) sb3[i]  = gb3[i];
    for (int i = tid; i < DI * HH;      i += 128) sWg1[i] = gWg1[i];
    for (int i = tid; i < HH;           i += 128) sbg1[i] = gbg1[i];
    for (int i = tid; i < HH * ED;      i += 128) sWg2[i] = gWg2[i];
    for (int i = tid; i < ED;           i += 128) sbg2[i] = gbg2[i];

    // ---- precompute per-lane B fragments (W2 bf16 split) ----
    for (int e = w * 2; e < w * 2 + 2; e++) {
        #pragma unroll
        for (int c = 0; c < 4; c++) {
            const int kf = c >> 1, nfh = c & 1;
            u32 hi4[4], lo4[4];
            #pragma unroll
            for (int p = 0; p < 2; p++) {
                const int n  = (nfh * 2 + p) * 8 + g;
                const int k0 = kf * 16 + 2 * q;
                const float w00 = gW2[e * 1024 + (k0    ) * 32 + n];
                const float w01 = gW2[e * 1024 + (k0 + 1) * 32 + n];
                const float w10 = gW2[e * 1024 + (k0 + 8) * 32 + n];
                const float w11 = gW2[e * 1024 + (k0 + 9) * 32 + n];
                const u32 h0 = bf16x2_of(w00, w01);
                const u32 h1 = bf16x2_of(w10, w11);
                hi4[p * 2 + 0] = h0;
                hi4[p * 2 + 1] = h1;
                lo4[p * 2 + 0] = bf16x2_of(w00 - bflo(h0), w01 - bfhi(h0));
                lo4[p * 2 + 1] = bf16x2_of(w10 - bflo(h1), w11 - bfhi(h1));
            }
            *(uint4*)(sBfrag + ((e * 8 + c    ) * 32 + lane) * 16) = make_uint4(hi4[0], hi4[1], hi4[2], hi4[3]);
            *(uint4*)(sBfrag + ((e * 8 + c + 4) * 32 + lane) * 16) = make_uint4(lo4[0], lo4[1], lo4[2], lo4[3]);
        }
    }
    __syncthreads();

    const int lim6 = B * DI;

    // ---- persistent per-warp tile loop (32 tokens per warp) ----
    for (int tile = blockIdx.x; tile < NT; tile += gridDim.x) {
        const int base = tile * 128 + w * 32;   // this warp's first token
        float* sxw = sx + w * 192;
        #pragma unroll
        for (int i = 0; i < 6; i++) {
            const int idx = base * DI + i * 32 + lane;
            sxw[i * 32 + lane] = (idx < lim6) ? gx[idx] : 0.0f;
        }
        __syncwarp();

        // x for this lane's 4 rows (tokens g+8m)
        float xm[4][DI];
        #pragma unroll
        for (int m = 0; m < 4; m++)
            #pragma unroll
            for (int d = 0; d < DI; d++)
                xm[m][d] = sxw[(g + 8 * m) * DI + d];

        // ---- gate for token (g + 8q) ----
        float gg[ED];
        {
            const float* xg = sxw + (g + 8 * q) * DI;
            float xv[DI];
            #pragma unroll
            for (int d = 0; d < DI; d++) xv[d] = xg[d];
            float hg[HH];
            #pragma unroll
            for (int j = 0; j < HH; j++) hg[j] = sbg1[j];
            #pragma unroll
            for (int d = 0; d < DI; d++) {
                const float xd = xv[d];
                #pragma unroll
                for (int j = 0; j < HH; j++) hg[j] = fmaf(xd, sWg1[d * HH + j], hg[j]);
            }
            #pragma unroll
            for (int j = 0; j < HH; j++) hg[j] = fmaxf(hg[j], 0.0f);
            float lg[ED];
            #pragma unroll
            for (int e = 0; e < ED; e++) lg[e] = sbg2[e];
            #pragma unroll
            for (int j = 0; j < HH; j++) {
                const float hj = hg[j];
                #pragma unroll
                for (int e = 0; e < ED; e++) lg[e] = fmaf(hj, sWg2[j * ED + e], lg[e]);
            }
            float mx = lg[0];
            #pragma unroll
            for (int e = 1; e < ED; e++) mx = fmaxf(mx, lg[e]);
            float s = 0.0f;
            #pragma unroll
            for (int e = 0; e < ED; e++) { lg[e] = __expf(lg[e] - mx); s += lg[e]; }
            const float inv = 1.0f / s;
            #pragma unroll
            for (int e = 0; e < ED; e++) gg[e] = lg[e] * inv;
        }

        float2 oP[4];
        #pragma unroll
        for (int m = 0; m < 4; m++) oP[m] = make_float2(0.0f, 0.0f);

        // ---- experts (fully unrolled) ----
        #pragma unroll
        for (int e = 0; e < ED; e++) {
            // layer 1 in fragment layout: acc[m][s] = pair (k=2q+8s, 2q+8s+1) of row g+8m
            u64 acc[4][4];
            #pragma unroll
            for (int s = 0; s < 4; s++) {
                const u64 bp = *(const u64*)&sb1[e * HH + 8 * s + 2 * q];
                acc[0][s] = bp; acc[1][s] = bp; acc[2][s] = bp; acc[3][s] = bp;
            }
            #pragma unroll
            for (int d = 0; d < DI; d++) {
                const u64 xd0 = pack_dup(xm[0][d]);
                const u64 xd1 = pack_dup(xm[1][d]);
                const u64 xd2 = pack_dup(xm[2][d]);
                const u64 xd3 = pack_dup(xm[3][d]);
                #pragma unroll
                for (int s = 0; s < 4; s++) {
                    const u64 wp = *(const u64*)&sW1[e * DI * HH + d * HH + 8 * s + 2 * q];
                    ffma2_acc(acc[0][s], xd0, wp);
                    ffma2_acc(acc[1][s], xd1, wp);
                    ffma2_acc(acc[2][s], xd2, wp);
                    ffma2_acc(acc[3][s], xd3, wp);
                }
            }

            // relu + bf16 split -> A fragments
            u32 ahi[2][2][4], alo[2][2][4];   // [mf][kf][reg]
            #pragma unroll
            for (int m = 0; m < 4; m++) {
                #pragma unroll
                for (int s = 0; s < 4; s++) {
                    const float2 f = unpack2(acc[m][s]);
                    const float h0 = fmaxf(f.x, 0.0f);
                    const float h1 = fmaxf(f.y, 0.0f);
                    const u32 hi = bf16x2_of(h0, h1);
                    const u32 lo = bf16x2_of(h0 - bflo(hi), h1 - bfhi(hi));
                    const int mf = m >> 1, r = m & 1, kf = s >> 1, kr = s & 1;
                    ahi[mf][kf][kr * 2 + r] = hi;
                    alo[mf][kf][kr * 2 + r] = lo;
                }
            }

            // B fragments (precomputed, per-lane, conflict-free LDS.128)
            uint4 cH[4], cL[4];
            #pragma unroll
            for (int c = 0; c < 4; c++) {
                cH[c] = *(const uint4*)(sBfrag + ((e * 8 + c    ) * 32 + lane) * 16);
                cL[c] = *(const uint4*)(sBfrag + ((e * 8 + c + 4) * 32 + lane) * 16);
            }

            // D = A_hi*B_hi + A_lo*B_hi + A_hi*B_lo
            float dd[2][4][4];
            #pragma unroll
            for (int mf = 0; mf < 2; mf++)
                #pragma unroll
                for (int nf = 0; nf < 4; nf++)
                    #pragma unroll
                    for (int r = 0; r < 4; r++) dd[mf][nf][r] = 0.0f;

            #pragma unroll
            for (int kf = 0; kf < 2; kf++) {
                #pragma unroll
                for (int nf = 0; nf < 4; nf++) {
                    const uint4 h4 = cH[kf * 2 + (nf >> 1)];
                    const uint4 l4 = cL[kf * 2 + (nf >> 1)];
                    const u32 b0h = (nf & 1) ? h4.z : h4.x;
                    const u32 b1h = (nf & 1) ? h4.w : h4.y;
                    const u32 b0l = (nf & 1) ? l4.z : l4.x;
                    const u32 b1l = (nf & 1) ? l4.w : l4.y;
                    #pragma unroll
                    for (int mf = 0; mf < 2; mf++) {
                        mma_bf16(dd[mf][nf][0], dd[mf][nf][1], dd[mf][nf][2], dd[mf][nf][3],
                                 ahi[mf][kf][0], ahi[mf][kf][1], ahi[mf][kf][2], ahi[mf][kf][3],
                                 b0h, b1h);
                        mma_bf16(dd[mf][nf][0], dd[mf][nf][1], dd[mf][nf][2], dd[mf][nf][3],
                                 alo[mf][kf][0], alo[mf][kf][1], alo[mf][kf][2], alo[mf][kf][3],
                                 b0h, b1h);
                        mma_bf16(dd[mf][nf][0], dd[mf][nf][1], dd[mf][nf][2], dd[mf][nf][3],
                                 ahi[mf][kf][0], ahi[mf][kf][1], ahi[mf][kf][2], ahi[mf][kf][3],
                                 b0l, b1l);
                    }
                }
            }

            // epilogue: bias + relu + layer3 + gate-weighted accumulate
            float2 b2p[4]; float4 w34[4];
            #pragma unroll
            for (int nf = 0; nf < 4; nf++) {
                b2p[nf] = *(const float2*)&sb2[e * HH + nf * 8 + 2 * q];
                w34[nf] = *(const float4*)&sW3[(e * HH + nf * 8 + 2 * q) * DO];
            }
            const float y0b = sb3[e * DO + 0];
            const float y1b = sb3[e * DO + 1];
            #pragma unroll
            for (int m = 0; m < 4; m++) {
                const int mf = m >> 1, r = m & 1;
                float y0 = y0b, y1 = y1b;
                #pragma unroll
                for (int nf = 0; nf < 4; nf++) {
                    const float ha = fmaxf(dd[mf][nf][r * 2 + 0] + b2p[nf].x, 0.0f);
                    const float hb = fmaxf(dd[mf][nf][r * 2 + 1] + b2p[nf].y, 0.0f);
                    y0 = fmaf(ha, w34[nf].x, y0);
                    y1 = fmaf(ha, w34[nf].y, y1);
                    y0 = fmaf(hb, w34[nf].z, y0);
                    y1 = fmaf(hb, w34[nf].w, y1);
                }
                const float ge = __shfl_sync(0xffffffffu, gg[e], (lane & 28) + m);
                oP[m].x = fmaf(ge, y0, oP[m].x);
                oP[m].y = fmaf(ge, y1, oP[m].y);
            }
        }

        // ---- quad butterfly reduction over col-partials, then write own token ----
        #pragma unroll
        for (int m = 0; m < 4; m++) {
            #pragma unroll
            for (int o = 1; o <= 2; o <<= 1) {
                oP[m].x += __shfl_xor_sync(0xffffffffu, oP[m].x, o);
                oP[m].y += __shfl_xor_sync(0xffffffffu, oP[m].y, o);
            }
        }
        float2 res = oP[0];
        if (q == 1) res = oP[1];
        if (q == 2) res = oP[2];
        if (q == 3) res = oP[3];
        const int t = base + g + 8 * q;
        if (t < B) ((float2*)gout)[t] = res;
    }
}

extern "C" void kernel_launch(void* const* d_in, const int* in_sizes, int n_in,
                              void* d_out, int out_size)
{
    const float* x   = (const float*)d_in[0];
    const float* W1  = (const float*)d_in[1];
    const float* b1  = (const float*)d_in[2];
    const float* W2  = (const float*)d_in[3];
    const float* b2  = (const float*)d_in[4];
    const float* W3  = (const float*)d_in[5];
    const float* b3  = (const float*)d_in[6];
    const float* Wg1 = (const float*)d_in[7];
    const float* bg1 = (const float*)d_in[8];
    const float* Wg2 = (const float*)d_in[9];
    const float* bg2 = (const float*)d_in[10];
    float* out = (float*)d_out;

    const int B  = in_sizes[0] / DI;
    const int NT = (B + 127) / 128;

    int nsm = 148;
    cudaDeviceGetAttribute(&nsm, cudaDevAttrMultiProcessorCount, 0);
    int grid = 4 * nsm;          // 4 CTAs/SM residency (regs=128, smem=48KB fit)
    if (grid > NT) grid = NT;

    moe_mma_kernel<<<grid, 128>>>(x, W1, b1, W2, b2, W3, b3,
                                  Wg1, bg1, Wg2, bg2, out, B, NT);
}

// round 6
// speedup vs baseline: 1.2140x; 1.2140x over previous
#include <cuda_runtime.h>
#include <cuda_bf16.h>
#include <cstdint>

// MoE dense 8-expert: D_IN=6, H=32, D_OUT=2, B=1M, fp32.
// R6: layer-1 ALSO on tensor cores (mma.m16n8k8 bf16 3-split, x-fragments
// built once per tile, b1 folded into the unused k=6 slot). Layer-1 D-frags
// feed layer-2 A-frags with no reshuffle. Layer-2 = R4's proven mma.m16n8k16
// path. Gate scalar. Grid = 2 CTAs/SM (R4 best config).

#define ED 8
#define DI 6
#define HH 32
#define DO 2

typedef unsigned long long u64;
typedef unsigned int u32;

// ---- helpers ----
__device__ __forceinline__ u32 bf16x2_of(float lo_e, float hi_e) {
    u32 r; asm("cvt.rn.bf16x2.f32 %0, %1, %2;" : "=r"(r) : "f"(hi_e), "f"(lo_e)); return r;
}
__device__ __forceinline__ float bflo(u32 p) { return __uint_as_float(p << 16); }
__device__ __forceinline__ float bfhi(u32 p) { return __uint_as_float(p & 0xffff0000u); }

__device__ __forceinline__ void mma_bf16(float& d0, float& d1, float& d2, float& d3,
                                         u32 a0, u32 a1, u32 a2, u32 a3,
                                         u32 b0, u32 b1) {
    asm("mma.sync.aligned.m16n8k16.row.col.f32.bf16.bf16.f32 "
        "{%0,%1,%2,%3}, {%4,%5,%6,%7}, {%8,%9}, {%0,%1,%2,%3};"
        : "+f"(d0), "+f"(d1), "+f"(d2), "+f"(d3)
        : "r"(a0), "r"(a1), "r"(a2), "r"(a3), "r"(b0), "r"(b1));
}
__device__ __forceinline__ void mma_bf16_k8(float& d0, float& d1, float& d2, float& d3,
                                            u32 a0, u32 a1, u32 b0) {
    asm("mma.sync.aligned.m16n8k8.row.col.f32.bf16.bf16.f32 "
        "{%0,%1,%2,%3}, {%4,%5}, {%6}, {%0,%1,%2,%3};"
        : "+f"(d0), "+f"(d1), "+f"(d2), "+f"(d3)
        : "r"(a0), "r"(a1), "r"(b0));
}

__global__ __launch_bounds__(128)
void moe_mma_kernel(const float* __restrict__ gx,
                    const float* __restrict__ gW1, const float* __restrict__ gb1,
                    const float* __restrict__ gW2, const float* __restrict__ gb2,
                    const float* __restrict__ gW3, const float* __restrict__ gb3,
                    const float* __restrict__ gWg1, const float* __restrict__ gbg1,
                    const float* __restrict__ gWg2, const float* __restrict__ gbg2,
                    float* __restrict__ gout, int B, int NT)
{
    __shared__ __align__(16) float sx[4 * 192];               // per-warp x tiles
    __shared__ __align__(16) char  sBfrag[ED * 8 * 32 * 16];  // layer-2 W2 frags (hi|lo)
    __shared__ __align__(16) char  sB1frag[ED * 2 * 32 * 16]; // layer-1 W1 frags (hi|lo), b1 folded @k=6
    __shared__ __align__(16) float sb2[ED * HH];
    __shared__ __align__(16) float sW3[ED * HH * DO];
    __shared__ __align__(16) float sb3[ED * DO];
    __shared__ __align__(16) float sWg1[DI * HH];
    __shared__ __align__(16) float sbg1[HH];
    __shared__ __align__(16) float sWg2[HH * ED];
    __shared__ __align__(16) float sbg2[ED];

    const int tid  = threadIdx.x;
    const int w    = tid >> 5;
    const int lane = tid & 31;
    const int g    = lane >> 2;   // groupID
    const int q    = lane & 3;    // threadID in group

    // ---- stage small weights (gate + epilogue) ----
    for (int i = tid; i < ED * HH;      i += 128) sb2[i]  = gb2[i];
    for (int i = tid; i < ED * HH * DO; i += 128) sW3[i]  = gW3[i];
    for (int i = tid; i < ED * DO;      i += 128) sb3[i]  = gb3[i];
    for (int i = tid; i < DI * HH;      i += 128) sWg1[i] = gWg1[i];
    for (int i = tid; i < HH;           i += 128) sbg1[i] = gbg1[i];
    for (int i = tid; i < HH * ED;      i += 128) sWg2[i] = gWg2[i];
    for (int i = tid; i < ED;           i += 128) sbg2[i] = gbg2[i];

    // ---- precompute per-lane B fragments ----
    for (int e = w * 2; e < w * 2 + 2; e++) {
        // layer-2 (W2, k16 frags: 4 hi chunks + 4 lo chunks) — same as R4
        #pragma unroll
        for (int c = 0; c < 4; c++) {
            const int kf = c >> 1, nfh = c & 1;
            u32 hi4[4], lo4[4];
            #pragma unroll
            for (int p = 0; p < 2; p++) {
                const int n  = (nfh * 2 + p) * 8 + g;
                const int k0 = kf * 16 + 2 * q;
                const float w00 = gW2[e * 1024 + (k0    ) * 32 + n];
                const float w01 = gW2[e * 1024 + (k0 + 1) * 32 + n];
                const float w10 = gW2[e * 1024 + (k0 + 8) * 32 + n];
                const float w11 = gW2[e * 1024 + (k0 + 9) * 32 + n];
                const u32 h0 = bf16x2_of(w00, w01);
                const u32 h1 = bf16x2_of(w10, w11);
                hi4[p * 2 + 0] = h0;
                hi4[p * 2 + 1] = h1;
                lo4[p * 2 + 0] = bf16x2_of(w00 - bflo(h0), w01 - bfhi(h0));
                lo4[p * 2 + 1] = bf16x2_of(w10 - bflo(h1), w11 - bfhi(h1));
            }
            *(uint4*)(sBfrag + ((e * 8 + c    ) * 32 + lane) * 16) = make_uint4(hi4[0], hi4[1], hi4[2], hi4[3]);
            *(uint4*)(sBfrag + ((e * 8 + c + 4) * 32 + lane) * 16) = make_uint4(lo4[0], lo4[1], lo4[2], lo4[3]);
        }
        // layer-1 (W1, k8 frags; q==3 carries b1 at k=6, 0 at k=7)
        {
            u32 hi4[4], lo4[4];
            #pragma unroll
            for (int nf = 0; nf < 4; nf++) {
                const int n = nf * 8 + g;
                float w0, w1;
                if (q < 3) {
                    w0 = gW1[e * 192 + (2 * q    ) * 32 + n];
                    w1 = gW1[e * 192 + (2 * q + 1) * 32 + n];
                } else {
                    w0 = gb1[e * 32 + n];   // k=6 slot: bias (A supplies 1.0)
                    w1 = 0.0f;              // k=7: unused
                }
                const u32 h = bf16x2_of(w0, w1);
                hi4[nf] = h;
                lo4[nf] = bf16x2_of(w0 - bflo(h), w1 - bfhi(h));
            }
            *(uint4*)(sB1frag + ((e * 2 + 0) * 32 + lane) * 16) = make_uint4(hi4[0], hi4[1], hi4[2], hi4[3]);
            *(uint4*)(sB1frag + ((e * 2 + 1) * 32 + lane) * 16) = make_uint4(lo4[0], lo4[1], lo4[2], lo4[3]);
        }
    }
    __syncthreads();

    const int lim6 = B * DI;

    // ---- persistent per-warp tile loop (32 tokens per warp) ----
    for (int tile = blockIdx.x; tile < NT; tile += gridDim.x) {
        const int base = tile * 128 + w * 32;
        float* sxw = sx + w * 192;
        #pragma unroll
        for (int i = 0; i < 6; i++) {
            const int idx = base * DI + i * 32 + lane;
            sxw[i * 32 + lane] = (idx < lim6) ? gx[idx] : 0.0f;
        }
        __syncwarp();

        // ---- build x A-fragments (k8), shared by all experts; k=6 slot = 1.0 ----
        u32 xhi[2][2], xlo[2][2];   // [mf][reg: row g / row g+8]
        #pragma unroll
        for (int mf = 0; mf < 2; mf++) {
            const int r0 = 16 * mf + g, r1 = r0 + 8;
            float v00, v01, v10, v11;
            if (q < 3) {
                v00 = sxw[r0 * DI + 2 * q]; v01 = sxw[r0 * DI + 2 * q + 1];
                v10 = sxw[r1 * DI + 2 * q]; v11 = sxw[r1 * DI + 2 * q + 1];
            } else {
                v00 = 1.0f; v01 = 0.0f; v10 = 1.0f; v11 = 0.0f;
            }
            const u32 h0 = bf16x2_of(v00, v01);
            const u32 h1 = bf16x2_of(v10, v11);
            xhi[mf][0] = h0; xhi[mf][1] = h1;
            xlo[mf][0] = bf16x2_of(v00 - bflo(h0), v01 - bfhi(h0));
            xlo[mf][1] = bf16x2_of(v10 - bflo(h1), v11 - bfhi(h1));
        }

        // ---- gate for token (g + 8q), scalar ----
        float gg[ED];
        {
            const float* xg = sxw + (g + 8 * q) * DI;
            float xv[DI];
            #pragma unroll
            for (int d = 0; d < DI; d++) xv[d] = xg[d];
            float hg[HH];
            #pragma unroll
            for (int j = 0; j < HH; j++) hg[j] = sbg1[j];
            #pragma unroll
            for (int d = 0; d < DI; d++) {
                const float xd = xv[d];
                #pragma unroll
                for (int j = 0; j < HH; j++) hg[j] = fmaf(xd, sWg1[d * HH + j], hg[j]);
            }
            #pragma unroll
            for (int j = 0; j < HH; j++) hg[j] = fmaxf(hg[j], 0.0f);
            float lg[ED];
            #pragma unroll
            for (int e = 0; e < ED; e++) lg[e] = sbg2[e];
            #pragma unroll
            for (int j = 0; j < HH; j++) {
                const float hj = hg[j];
                #pragma unroll
                for (int e = 0; e < ED; e++) lg[e] = fmaf(hj, sWg2[j * ED + e], lg[e]);
            }
            float mx = lg[0];
            #pragma unroll
            for (int e = 1; e < ED; e++) mx = fmaxf(mx, lg[e]);
            float s = 0.0f;
            #pragma unroll
            for (int e = 0; e < ED; e++) { lg[e] = __expf(lg[e] - mx); s += lg[e]; }
            const float inv = 1.0f / s;
            #pragma unroll
            for (int e = 0; e < ED; e++) gg[e] = lg[e] * inv;
        }

        float2 oP[4];
        #pragma unroll
        for (int m = 0; m < 4; m++) oP[m] = make_float2(0.0f, 0.0f);

        // ---- experts ----
        #pragma unroll
        for (int e = 0; e < ED; e++) {
            // layer 1 via mma.k8: h1 = x @ W1[e] (+b1 via k=6 slot)
            const uint4 bh4 = *(const uint4*)(sB1frag + ((e * 2 + 0) * 32 + lane) * 16);
            const uint4 bl4 = *(const uint4*)(sB1frag + ((e * 2 + 1) * 32 + lane) * 16);
            float h1d[2][4][4];
            #pragma unroll
            for (int mf = 0; mf < 2; mf++)
                #pragma unroll
                for (int nf = 0; nf < 4; nf++)
                    #pragma unroll
                    for (int r = 0; r < 4; r++) h1d[mf][nf][r] = 0.0f;
            #pragma unroll
            for (int nf = 0; nf < 4; nf++) {
                const u32 bh = (nf == 0) ? bh4.x : (nf == 1) ? bh4.y : (nf == 2) ? bh4.z : bh4.w;
                const u32 bl = (nf == 0) ? bl4.x : (nf == 1) ? bl4.y : (nf == 2) ? bl4.z : bl4.w;
                #pragma unroll
                for (int mf = 0; mf < 2; mf++) {
                    mma_bf16_k8(h1d[mf][nf][0], h1d[mf][nf][1], h1d[mf][nf][2], h1d[mf][nf][3],
                                xhi[mf][0], xhi[mf][1], bh);
                    mma_bf16_k8(h1d[mf][nf][0], h1d[mf][nf][1], h1d[mf][nf][2], h1d[mf][nf][3],
                                xlo[mf][0], xlo[mf][1], bh);
                    mma_bf16_k8(h1d[mf][nf][0], h1d[mf][nf][1], h1d[mf][nf][2], h1d[mf][nf][3],
                                xhi[mf][0], xhi[mf][1], bl);
                }
            }

            // relu + bf16 split: D-frags -> layer-2 A-frags (no reshuffle)
            u32 ahi[2][2][4], alo[2][2][4];   // [mf][kf][reg]
            #pragma unroll
            for (int mf = 0; mf < 2; mf++) {
                #pragma unroll
                for (int kf = 0; kf < 2; kf++) {
                    #pragma unroll
                    for (int half = 0; half < 2; half++) {     // half0: a0/a1 (nf=2kf), half1: a2/a3 (nf=2kf+1)
                        const int nf = 2 * kf + half;
                        const float f0 = fmaxf(h1d[mf][nf][0], 0.0f);
                        const float f1 = fmaxf(h1d[mf][nf][1], 0.0f);
                        const float f2 = fmaxf(h1d[mf][nf][2], 0.0f);
                        const float f3 = fmaxf(h1d[mf][nf][3], 0.0f);
                        const u32 hA = bf16x2_of(f0, f1);   // row g
                        const u32 hB = bf16x2_of(f2, f3);   // row g+8
                        ahi[mf][kf][half * 2 + 0] = hA;
                        ahi[mf][kf][half * 2 + 1] = hB;
                        alo[mf][kf][half * 2 + 0] = bf16x2_of(f0 - bflo(hA), f1 - bfhi(hA));
                        alo[mf][kf][half * 2 + 1] = bf16x2_of(f2 - bflo(hB), f3 - bfhi(hB));
                    }
                }
            }

            // layer-2 B fragments (precomputed, conflict-free LDS.128)
            uint4 cH[4], cL[4];
            #pragma unroll
            for (int c = 0; c < 4; c++) {
                cH[c] = *(const uint4*)(sBfrag + ((e * 8 + c    ) * 32 + lane) * 16);
                cL[c] = *(const uint4*)(sBfrag + ((e * 8 + c + 4) * 32 + lane) * 16);
            }

            // layer-2: D = A_hi*B_hi + A_lo*B_hi + A_hi*B_lo
            float dd[2][4][4];
            #pragma unroll
            for (int mf = 0; mf < 2; mf++)
                #pragma unroll
                for (int nf = 0; nf < 4; nf++)
                    #pragma unroll
                    for (int r = 0; r < 4; r++) dd[mf][nf][r] = 0.0f;

            #pragma unroll
            for (int kf = 0; kf < 2; kf++) {
                #pragma unroll
                for (int nf = 0; nf < 4; nf++) {
                    const uint4 h4 = cH[kf * 2 + (nf >> 1)];
                    const uint4 l4 = cL[kf * 2 + (nf >> 1)];
                    const u32 b0h = (nf & 1) ? h4.z : h4.x;
                    const u32 b1h = (nf & 1) ? h4.w : h4.y;
                    const u32 b0l = (nf & 1) ? l4.z : l4.x;
                    const u32 b1l = (nf & 1) ? l4.w : l4.y;
                    #pragma unroll
                    for (int mf = 0; mf < 2; mf++) {
                        mma_bf16(dd[mf][nf][0], dd[mf][nf][1], dd[mf][nf][2], dd[mf][nf][3],
                                 ahi[mf][kf][0], ahi[mf][kf][1], ahi[mf][kf][2], ahi[mf][kf][3],
                                 b0h, b1h);
                        mma_bf16(dd[mf][nf][0], dd[mf][nf][1], dd[mf][nf][2], dd[mf][nf][3],
                                 alo[mf][kf][0], alo[mf][kf][1], alo[mf][kf][2], alo[mf][kf][3],
                                 b0h, b1h);
                        mma_bf16(dd[mf][nf][0], dd[mf][nf][1], dd[mf][nf][2], dd[mf][nf][3],
                                 ahi[mf][kf][0], ahi[mf][kf][1], ahi[mf][kf][2], ahi[mf][kf][3],
                                 b0l, b1l);
                    }
                }
            }

            // epilogue: bias + relu + layer3 + gate-weighted accumulate
            float2 b2p[4]; float4 w34[4];
            #pragma unroll
            for (int nf = 0; nf < 4; nf++) {
                b2p[nf] = *(const float2*)&sb2[e * HH + nf * 8 + 2 * q];
                w34[nf] = *(const float4*)&sW3[(e * HH + nf * 8 + 2 * q) * DO];
            }
            const float y0b = sb3[e * DO + 0];
            const float y1b = sb3[e * DO + 1];
            #pragma unroll
            for (int m = 0; m < 4; m++) {
                const int mf = m >> 1, r = m & 1;
                float y0 = y0b, y1 = y1b;
                #pragma unroll
                for (int nf = 0; nf < 4; nf++) {
                    const float ha = fmaxf(dd[mf][nf][r * 2 + 0] + b2p[nf].x, 0.0f);
                    const float hb = fmaxf(dd[mf][nf][r * 2 + 1] + b2p[nf].y, 0.0f);
                    y0 = fmaf(ha, w34[nf].x, y0);
                    y1 = fmaf(ha, w34[nf].y, y1);
                    y0 = fmaf(hb, w34[nf].z, y0);
                    y1 = fmaf(hb, w34[nf].w, y1);
                }
                const float ge = __shfl_sync(0xffffffffu, gg[e], (lane & 28) + m);
                oP[m].x = fmaf(ge, y0, oP[m].x);
                oP[m].y = fmaf(ge, y1, oP[m].y);
            }
        }

        // ---- quad butterfly reduction, write own token ----
        #pragma unroll
        for (int m = 0; m < 4; m++) {
            #pragma unroll
            for (int o = 1; o <= 2; o <<= 1) {
                oP[m].x += __shfl_xor_sync(0xffffffffu, oP[m].x, o);
                oP[m].y += __shfl_xor_sync(0xffffffffu, oP[m].y, o);
            }
        }
        float2 res = oP[0];
        if (q == 1) res = oP[1];
        if (q == 2) res = oP[2];
        if (q == 3) res = oP[3];
        const int t = base + g + 8 * q;
        if (t < B) ((float2*)gout)[t] = res;
    }
}

extern "C" void kernel_launch(void* const* d_in, const int* in_sizes, int n_in,
                              void* d_out, int out_size)
{
    const float* x   = (const float*)d_in[0];
    const float* W1  = (const float*)d_in[1];
    const float* b1  = (const float*)d_in[2];
    const float* W2  = (const float*)d_in[3];
    const float* b2  = (const float*)d_in[4];
    const float* W3  = (const float*)d_in[5];
    const float* b3  = (const float*)d_in[6];
    const float* Wg1 = (const float*)d_in[7];
    const float* bg1 = (const float*)d_in[8];
    const float* Wg2 = (const float*)d_in[9];
    const float* bg2 = (const float*)d_in[10];
    float* out = (float*)d_out;

    const int B  = in_sizes[0] / DI;
    const int NT = (B + 127) / 128;

    int nsm = 148;
    cudaDeviceGetAttribute(&nsm, cudaDevAttrMultiProcessorCount, 0);
    int grid = 2 * nsm;          // R4's best residency
    if (grid > NT) grid = NT;

    moe_mma_kernel<<<grid, 128>>>(x, W1, b1, W2, b2, W3, b3,
                                  Wg1, bg1, Wg2, bg2, out, B, NT);
}

// round 7
// speedup vs baseline: 1.2463x; 1.0265x over previous
#include <cuda_runtime.h>
#include <cuda_bf16.h>
#include <cstdint>

// MoE dense 8-expert: D_IN=6, H=32, D_OUT=2, B=1M, fp32.
// R7 = R6 (both layers on mma.sync bf16 3-split) minus dead instructions:
//  - accumulator zero-inits replaced by MMA C-operand (zeros for layer-1,
//    b2-bias fragment for layer-2; epilogue +b2 FADDs deleted too)
//  - gate network packed with fma.rn.f32x2 (halves its FFMA count)
// Grid = 2 CTAs/SM (best measured residency).

#define ED 8
#define DI 6
#define HH 32
#define DO 2

typedef unsigned long long u64;
typedef unsigned int u32;

// ---- scalar helpers ----
__device__ __forceinline__ void ffma2_acc(u64& acc, u64 a, u64 b) {
    asm("fma.rn.f32x2 %0, %1, %2, %0;" : "+l"(acc) : "l"(a), "l"(b));
}
__device__ __forceinline__ u64 pack_dup(float v) {
    u64 r; asm("mov.b64 %0, {%1, %1};" : "=l"(r) : "r"(__float_as_uint(v))); return r;
}
__device__ __forceinline__ float2 unpack2(u64 v) {
    float2 f; asm("mov.b64 {%0, %1}, %2;" : "=f"(f.x), "=f"(f.y) : "l"(v)); return f;
}
__device__ __forceinline__ u32 bf16x2_of(float lo_e, float hi_e) {
    u32 r; asm("cvt.rn.bf16x2.f32 %0, %1, %2;" : "=r"(r) : "f"(hi_e), "f"(lo_e)); return r;
}
__device__ __forceinline__ float bflo(u32 p) { return __uint_as_float(p << 16); }
__device__ __forceinline__ float bfhi(u32 p) { return __uint_as_float(p & 0xffff0000u); }

// ---- MMA helpers ----
__device__ __forceinline__ void mma_bf16(float& d0, float& d1, float& d2, float& d3,
                                         u32 a0, u32 a1, u32 a2, u32 a3,
                                         u32 b0, u32 b1) {
    asm("mma.sync.aligned.m16n8k16.row.col.f32.bf16.bf16.f32 "
        "{%0,%1,%2,%3}, {%4,%5,%6,%7}, {%8,%9}, {%0,%1,%2,%3};"
        : "+f"(d0), "+f"(d1), "+f"(d2), "+f"(d3)
        : "r"(a0), "r"(a1), "r"(a2), "r"(a3), "r"(b0), "r"(b1));
}
// first-touch variant: D = A*B + C (C given explicitly; kills zero-init)
__device__ __forceinline__ void mma_bf16_c(float& d0, float& d1, float& d2, float& d3,
                                           u32 a0, u32 a1, u32 a2, u32 a3,
                                           u32 b0, u32 b1,
                                           float c0, float c1, float c2, float c3) {
    asm("mma.sync.aligned.m16n8k16.row.col.f32.bf16.bf16.f32 "
        "{%0,%1,%2,%3}, {%4,%5,%6,%7}, {%8,%9}, {%10,%11,%12,%13};"
        : "=f"(d0), "=f"(d1), "=f"(d2), "=f"(d3)
        : "r"(a0), "r"(a1), "r"(a2), "r"(a3), "r"(b0), "r"(b1),
          "f"(c0), "f"(c1), "f"(c2), "f"(c3));
}
__device__ __forceinline__ void mma_bf16_k8(float& d0, float& d1, float& d2, float& d3,
                                            u32 a0, u32 a1, u32 b0) {
    asm("mma.sync.aligned.m16n8k8.row.col.f32.bf16.bf16.f32 "
        "{%0,%1,%2,%3}, {%4,%5}, {%6}, {%0,%1,%2,%3};"
        : "+f"(d0), "+f"(d1), "+f"(d2), "+f"(d3)
        : "r"(a0), "r"(a1), "r"(b0));
}
__device__ __forceinline__ void mma_bf16_k8_c(float& d0, float& d1, float& d2, float& d3,
                                              u32 a0, u32 a1, u32 b0,
                                              float c0, float c1, float c2, float c3) {
    asm("mma.sync.aligned.m16n8k8.row.col.f32.bf16.bf16.f32 "
        "{%0,%1,%2,%3}, {%4,%5}, {%6}, {%7,%8,%9,%10};"
        : "=f"(d0), "=f"(d1), "=f"(d2), "=f"(d3)
        : "r"(a0), "r"(a1), "r"(b0),
          "f"(c0), "f"(c1), "f"(c2), "f"(c3));
}

__global__ __launch_bounds__(128)
void moe_mma_kernel(const float* __restrict__ gx,
                    const float* __restrict__ gW1, const float* __restrict__ gb1,
                    const float* __restrict__ gW2, const float* __restrict__ gb2,
                    const float* __restrict__ gW3, const float* __restrict__ gb3,
                    const float* __restrict__ gWg1, const float* __restrict__ gbg1,
                    const float* __restrict__ gWg2, const float* __restrict__ gbg2,
                    float* __restrict__ gout, int B, int NT)
{
    __shared__ __align__(16) float sx[4 * 192];               // per-warp x tiles
    __shared__ __align__(16) char  sBfrag[ED * 8 * 32 * 16];  // layer-2 W2 frags (hi|lo)
    __shared__ __align__(16) char  sB1frag[ED * 2 * 32 * 16]; // layer-1 W1 frags, b1 @k=6
    __shared__ __align__(16) float sb2[ED * HH];
    __shared__ __align__(16) float sW3[ED * HH * DO];
    __shared__ __align__(16) float sb3[ED * DO];
    __shared__ __align__(16) float sWg1[DI * HH];
    __shared__ __align__(16) float sbg1[HH];
    __shared__ __align__(16) float sWg2[HH * ED];
    __shared__ __align__(16) float sbg2[ED];

    const int tid  = threadIdx.x;
    const int w    = tid >> 5;
    const int lane = tid & 31;
    const int g    = lane >> 2;   // groupID
    const int q    = lane & 3;    // threadID in group

    // ---- stage small weights ----
    for (int i = tid; i < ED * HH;      i += 128) sb2[i]  = gb2[i];
    for (int i = tid; i < ED * HH * DO; i += 128) sW3[i]  = gW3[i];
    for (int i = tid; i < ED * DO;      i += 128) sb3[i]  = gb3[i];
    for (int i = tid; i < DI * HH;      i += 128) sWg1[i] = gWg1[i];
    for (int i = tid; i < HH;           i += 128) sbg1[i] = gbg1[i];
    for (int i = tid; i < HH * ED;      i += 128) sWg2[i] = gWg2[i];
    for (int i = tid; i < ED;           i += 128) sbg2[i] = gbg2[i];

    // ---- precompute per-lane B fragments ----
    for (int e = w * 2; e < w * 2 + 2; e++) {
        // layer-2 (W2, k16 frags: 4 hi chunks + 4 lo chunks)
        #pragma unroll
        for (int c = 0; c < 4; c++) {
            const int kf = c >> 1, nfh = c & 1;
            u32 hi4[4], lo4[4];
            #pragma unroll
            for (int p = 0; p < 2; p++) {
                const int n  = (nfh * 2 + p) * 8 + g;
                const int k0 = kf * 16 + 2 * q;
                const float w00 = gW2[e * 1024 + (k0    ) * 32 + n];
                const float w01 = gW2[e * 1024 + (k0 + 1) * 32 + n];
                const float w10 = gW2[e * 1024 + (k0 + 8) * 32 + n];
                const float w11 = gW2[e * 1024 + (k0 + 9) * 32 + n];
                const u32 h0 = bf16x2_of(w00, w01);
                const u32 h1 = bf16x2_of(w10, w11);
                hi4[p * 2 + 0] = h0;
                hi4[p * 2 + 1] = h1;
                lo4[p * 2 + 0] = bf16x2_of(w00 - bflo(h0), w01 - bfhi(h0));
                lo4[p * 2 + 1] = bf16x2_of(w10 - bflo(h1), w11 - bfhi(h1));
            }
            *(uint4*)(sBfrag + ((e * 8 + c    ) * 32 + lane) * 16) = make_uint4(hi4[0], hi4[1], hi4[2], hi4[3]);
            *(uint4*)(sBfrag + ((e * 8 + c + 4) * 32 + lane) * 16) = make_uint4(lo4[0], lo4[1], lo4[2], lo4[3]);
        }
        // layer-1 (W1, k8 frags; q==3 carries b1 at k=6, 0 at k=7)
        {
            u32 hi4[4], lo4[4];
            #pragma unroll
            for (int nf = 0; nf < 4; nf++) {
                const int n = nf * 8 + g;
                float w0, w1;
                if (q < 3) {
                    w0 = gW1[e * 192 + (2 * q    ) * 32 + n];
                    w1 = gW1[e * 192 + (2 * q + 1) * 32 + n];
                } else {
                    w0 = gb1[e * 32 + n];
                    w1 = 0.0f;
                }
                const u32 h = bf16x2_of(w0, w1);
                hi4[nf] = h;
                lo4[nf] = bf16x2_of(w0 - bflo(h), w1 - bfhi(h));
            }
            *(uint4*)(sB1frag + ((e * 2 + 0) * 32 + lane) * 16) = make_uint4(hi4[0], hi4[1], hi4[2], hi4[3]);
            *(uint4*)(sB1frag + ((e * 2 + 1) * 32 + lane) * 16) = make_uint4(lo4[0], lo4[1], lo4[2], lo4[3]);
        }
    }
    __syncthreads();

    const int lim6 = B * DI;
    const float fz = 0.0f;   // zero C-operand regs

    // ---- persistent per-warp tile loop (32 tokens per warp) ----
    for (int tile = blockIdx.x; tile < NT; tile += gridDim.x) {
        const int base = tile * 128 + w * 32;
        float* sxw = sx + w * 192;
        #pragma unroll
        for (int i = 0; i < 6; i++) {
            const int idx = base * DI + i * 32 + lane;
            sxw[i * 32 + lane] = (idx < lim6) ? gx[idx] : 0.0f;
        }
        __syncwarp();

        // ---- build x A-fragments (k8), shared by all experts; k=6 slot = 1.0 ----
        u32 xhi[2][2], xlo[2][2];
        #pragma unroll
        for (int mf = 0; mf < 2; mf++) {
            const int r0 = 16 * mf + g, r1 = r0 + 8;
            float v00, v01, v10, v11;
            if (q < 3) {
                v00 = sxw[r0 * DI + 2 * q]; v01 = sxw[r0 * DI + 2 * q + 1];
                v10 = sxw[r1 * DI + 2 * q]; v11 = sxw[r1 * DI + 2 * q + 1];
            } else {
                v00 = 1.0f; v01 = 0.0f; v10 = 1.0f; v11 = 0.0f;
            }
            const u32 h0 = bf16x2_of(v00, v01);
            const u32 h1 = bf16x2_of(v10, v11);
            xhi[mf][0] = h0; xhi[mf][1] = h1;
            xlo[mf][0] = bf16x2_of(v00 - bflo(h0), v01 - bfhi(h0));
            xlo[mf][1] = bf16x2_of(v10 - bflo(h1), v11 - bfhi(h1));
        }

        // ---- gate for token (g + 8q): packed FFMA2 ----
        float gg[ED];
        {
            const float* xg = sxw + (g + 8 * q) * DI;
            u64 gacc[HH / 2];
            const u64* bg1p = (const u64*)sbg1;
            #pragma unroll
            for (int i = 0; i < HH / 2; i++) gacc[i] = bg1p[i];
            #pragma unroll
            for (int d = 0; d < DI; d++) {
                const u64 xd = pack_dup(xg[d]);
                const u64* wr = (const u64*)(sWg1 + d * HH);
                #pragma unroll
                for (int i = 0; i < HH / 2; i++) ffma2_acc(gacc[i], xd, wr[i]);
            }
            u64 lacc[ED / 2];
            const u64* bg2p = (const u64*)sbg2;
            #pragma unroll
            for (int i = 0; i < ED / 2; i++) lacc[i] = bg2p[i];
            #pragma unroll
            for (int i = 0; i < HH / 2; i++) {
                const float2 t = unpack2(gacc[i]);
                const u64 hj0 = pack_dup(fmaxf(t.x, 0.0f));
                const u64 hj1 = pack_dup(fmaxf(t.y, 0.0f));
                const u64* wr0 = (const u64*)(sWg2 + (2 * i    ) * ED);
                const u64* wr1 = (const u64*)(sWg2 + (2 * i + 1) * ED);
                #pragma unroll
                for (int k2 = 0; k2 < ED / 2; k2++) {
                    ffma2_acc(lacc[k2], hj0, wr0[k2]);
                    ffma2_acc(lacc[k2], hj1, wr1[k2]);
                }
            }
            float lg[ED];
            #pragma unroll
            for (int i = 0; i < ED / 2; i++) {
                const float2 t = unpack2(lacc[i]);
                lg[2 * i] = t.x; lg[2 * i + 1] = t.y;
            }
            float mx = lg[0];
            #pragma unroll
            for (int e = 1; e < ED; e++) mx = fmaxf(mx, lg[e]);
            float s = 0.0f;
            #pragma unroll
            for (int e = 0; e < ED; e++) { lg[e] = __expf(lg[e] - mx); s += lg[e]; }
            const float inv = 1.0f / s;
            #pragma unroll
            for (int e = 0; e < ED; e++) gg[e] = lg[e] * inv;
        }

        float2 oP[4];
        #pragma unroll
        for (int m = 0; m < 4; m++) oP[m] = make_float2(0.0f, 0.0f);

        // ---- experts ----
        #pragma unroll
        for (int e = 0; e < ED; e++) {
            // layer 1 via mma.k8: h1 = x @ W1[e] (+b1 via k=6 slot); C = zeros
            const uint4 bh4 = *(const uint4*)(sB1frag + ((e * 2 + 0) * 32 + lane) * 16);
            const uint4 bl4 = *(const uint4*)(sB1frag + ((e * 2 + 1) * 32 + lane) * 16);
            float h1d[2][4][4];
            #pragma unroll
            for (int nf = 0; nf < 4; nf++) {
                const u32 bh = (nf == 0) ? bh4.x : (nf == 1) ? bh4.y : (nf == 2) ? bh4.z : bh4.w;
                const u32 bl = (nf == 0) ? bl4.x : (nf == 1) ? bl4.y : (nf == 2) ? bl4.z : bl4.w;
                #pragma unroll
                for (int mf = 0; mf < 2; mf++) {
                    mma_bf16_k8_c(h1d[mf][nf][0], h1d[mf][nf][1], h1d[mf][nf][2], h1d[mf][nf][3],
                                  xhi[mf][0], xhi[mf][1], bh, fz, fz, fz, fz);
                    mma_bf16_k8(h1d[mf][nf][0], h1d[mf][nf][1], h1d[mf][nf][2], h1d[mf][nf][3],
                                xlo[mf][0], xlo[mf][1], bh);
                    mma_bf16_k8(h1d[mf][nf][0], h1d[mf][nf][1], h1d[mf][nf][2], h1d[mf][nf][3],
                                xhi[mf][0], xhi[mf][1], bl);
                }
            }

            // relu + bf16 split: D-frags -> layer-2 A-frags (no reshuffle)
            u32 ahi[2][2][4], alo[2][2][4];
            #pragma unroll
            for (int mf = 0; mf < 2; mf++) {
                #pragma unroll
                for (int kf = 0; kf < 2; kf++) {
                    #pragma unroll
                    for (int half = 0; half < 2; half++) {
                        const int nf = 2 * kf + half;
                        const float f0 = fmaxf(h1d[mf][nf][0], 0.0f);
                        const float f1 = fmaxf(h1d[mf][nf][1], 0.0f);
                        const float f2 = fmaxf(h1d[mf][nf][2], 0.0f);
                        const float f3 = fmaxf(h1d[mf][nf][3], 0.0f);
                        const u32 hA = bf16x2_of(f0, f1);
                        const u32 hB = bf16x2_of(f2, f3);
                        ahi[mf][kf][half * 2 + 0] = hA;
                        ahi[mf][kf][half * 2 + 1] = hB;
                        alo[mf][kf][half * 2 + 0] = bf16x2_of(f0 - bflo(hA), f1 - bfhi(hA));
                        alo[mf][kf][half * 2 + 1] = bf16x2_of(f2 - bflo(hB), f3 - bfhi(hB));
                    }
                }
            }

            // layer-2 B fragments + b2 bias fragments
            uint4 cH[4], cL[4];
            #pragma unroll
            for (int c = 0; c < 4; c++) {
                cH[c] = *(const uint4*)(sBfrag + ((e * 8 + c    ) * 32 + lane) * 16);
                cL[c] = *(const uint4*)(sBfrag + ((e * 8 + c + 4) * 32 + lane) * 16);
            }
            float2 b2p[4];
            #pragma unroll
            for (int nf = 0; nf < 4; nf++) b2p[nf] = *(const float2*)&sb2[e * HH + nf * 8 + 2 * q];

            // layer-2: D = A_hi*B_hi + A_lo*B_hi + A_hi*B_lo, C(first) = b2
            float dd[2][4][4];
            #pragma unroll
            for (int nf = 0; nf < 4; nf++) {
                const uint4 h40 = cH[0 * 2 + (nf >> 1)];
                const uint4 l40 = cL[0 * 2 + (nf >> 1)];
                const uint4 h41 = cH[1 * 2 + (nf >> 1)];
                const uint4 l41 = cL[1 * 2 + (nf >> 1)];
                const u32 b0h0 = (nf & 1) ? h40.z : h40.x;
                const u32 b1h0 = (nf & 1) ? h40.w : h40.y;
                const u32 b0l0 = (nf & 1) ? l40.z : l40.x;
                const u32 b1l0 = (nf & 1) ? l40.w : l40.y;
                const u32 b0h1 = (nf & 1) ? h41.z : h41.x;
                const u32 b1h1 = (nf & 1) ? h41.w : h41.y;
                const u32 b0l1 = (nf & 1) ? l41.z : l41.x;
                const u32 b1l1 = (nf & 1) ? l41.w : l41.y;
                #pragma unroll
                for (int mf = 0; mf < 2; mf++) {
                    mma_bf16_c(dd[mf][nf][0], dd[mf][nf][1], dd[mf][nf][2], dd[mf][nf][3],
                               ahi[mf][0][0], ahi[mf][0][1], ahi[mf][0][2], ahi[mf][0][3],
                               b0h0, b1h0,
                               b2p[nf].x, b2p[nf].y, b2p[nf].x, b2p[nf].y);
                    mma_bf16(dd[mf][nf][0], dd[mf][nf][1], dd[mf][nf][2], dd[mf][nf][3],
                             alo[mf][0][0], alo[mf][0][1], alo[mf][0][2], alo[mf][0][3],
                             b0h0, b1h0);
                    mma_bf16(dd[mf][nf][0], dd[mf][nf][1], dd[mf][nf][2], dd[mf][nf][3],
                             ahi[mf][0][0], ahi[mf][0][1], ahi[mf][0][2], ahi[mf][0][3],
                             b0l0, b1l0);
                    mma_bf16(dd[mf][nf][0], dd[mf][nf][1], dd[mf][nf][2], dd[mf][nf][3],
                             ahi[mf][1][0], ahi[mf][1][1], ahi[mf][1][2], ahi[mf][1][3],
                             b0h1, b1h1);
                    mma_bf16(dd[mf][nf][0], dd[mf][nf][1], dd[mf][nf][2], dd[mf][nf][3],
                             alo[mf][1][0], alo[mf][1][1], alo[mf][1][2], alo[mf][1][3],
                             b0h1, b1h1);
                    mma_bf16(dd[mf][nf][0], dd[mf][nf][1], dd[mf][nf][2], dd[mf][nf][3],
                             ahi[mf][1][0], ahi[mf][1][1], ahi[mf][1][2], ahi[mf][1][3],
                             b0l1, b1l1);
                }
            }

            // epilogue: relu + layer3 + gate-weighted accumulate (b2 already in D)
            float4 w34[4];
            #pragma unroll
            for (int nf = 0; nf < 4; nf++)
                w34[nf] = *(const float4*)&sW3[(e * HH + nf * 8 + 2 * q) * DO];
            const float y0b = sb3[e * DO + 0];
            const float y1b = sb3[e * DO + 1];
            #pragma unroll
            for (int m = 0; m < 4; m++) {
                const int mf = m >> 1, r = m & 1;
                float y0 = y0b, y1 = y1b;
                #pragma unroll
                for (int nf = 0; nf < 4; nf++) {
                    const float ha = fmaxf(dd[mf][nf][r * 2 + 0], 0.0f);
                    const float hb = fmaxf(dd[mf][nf][r * 2 + 1], 0.0f);
                    y0 = fmaf(ha, w34[nf].x, y0);
                    y1 = fmaf(ha, w34[nf].y, y1);
                    y0 = fmaf(hb, w34[nf].z, y0);
                    y1 = fmaf(hb, w34[nf].w, y1);
                }
                const float ge = __shfl_sync(0xffffffffu, gg[e], (lane & 28) + m);
                oP[m].x = fmaf(ge, y0, oP[m].x);
                oP[m].y = fmaf(ge, y1, oP[m].y);
            }
        }

        // ---- quad butterfly reduction, write own token ----
        #pragma unroll
        for (int m = 0; m < 4; m++) {
            #pragma unroll
            for (int o = 1; o <= 2; o <<= 1) {
                oP[m].x += __shfl_xor_sync(0xffffffffu, oP[m].x, o);
                oP[m].y += __shfl_xor_sync(0xffffffffu, oP[m].y, o);
            }
        }
        float2 res = oP[0];
        if (q == 1) res = oP[1];
        if (q == 2) res = oP[2];
        if (q == 3) res = oP[3];
        const int t = base + g + 8 * q;
        if (t < B) ((float2*)gout)[t] = res;
    }
}

extern "C" void kernel_launch(void* const* d_in, const int* in_sizes, int n_in,
                              void* d_out, int out_size)
{
    const float* x   = (const float*)d_in[0];
    const float* W1  = (const float*)d_in[1];
    const float* b1  = (const float*)d_in[2];
    const float* W2  = (const float*)d_in[3];
    const float* b2  = (const float*)d_in[4];
    const float* W3  = (const float*)d_in[5];
    const float* b3  = (const float*)d_in[6];
    const float* Wg1 = (const float*)d_in[7];
    const float* bg1 = (const float*)d_in[8];
    const float* Wg2 = (const float*)d_in[9];
    const float* bg2 = (const float*)d_in[10];
    float* out = (float*)d_out;

    const int B  = in_sizes[0] / DI;
    const int NT = (B + 127) / 128;

    int nsm = 148;
    cudaDeviceGetAttribute(&nsm, cudaDevAttrMultiProcessorCount, 0);
    int grid = 2 * nsm;
    if (grid > NT) grid = NT;

    moe_mma_kernel<<<grid, 128>>>(x, W1, b1, W2, b2, W3, b3,
                                  Wg1, bg1, Wg2, bg2, out, B, NT);
}